// round 2
// baseline (speedup 1.0000x reference)
#include <cuda_runtime.h>
#include <math.h>

#define NN 100000
#define NE 1600000
#define MAXIT 50
#define THREADS 512

// ---------------- device global scratch (no runtime allocation allowed) ----------------
__device__ __align__(16) float g_state[2][NN * 8];   // padded: 8 floats per node (5 used)
__device__ __align__(16) float4 g_pre4[NE * 4];      // per edge: 15 f32 pre-acts + src bits in slot .w of [3]
__device__ __align__(8)  int2   g_rv[NE];            // {row, val_bits}
__device__ unsigned g_barc;                          // barrier counter (zero-init)
__device__ unsigned g_barg;                          // barrier generation
__device__ int      g_flags[64];                     // per-iteration convergence flags

// ---------------- fast math ----------------
__device__ __forceinline__ float fast_tanh(float x) {
    // tanh(x) = 1 - 2/(exp(2x)+1); ex2.approx + rcp.approx ~1e-6 abs err
    float t;
    asm("ex2.approx.f32 %0, %1;" : "=f"(t) : "f"(x * 2.885390081777927f)); // exp(2x)
    float r;
    asm("rcp.approx.f32 %0, %1;" : "=f"(r) : "f"(t + 1.0f));
    return fmaf(-2.0f, r, 1.0f);
}
__device__ __forceinline__ float fast_exp(float x) {
    float t;
    asm("ex2.approx.f32 %0, %1;" : "=f"(t) : "f"(x * 1.4426950408889634f));
    return t;
}

// ---------------- grid barrier (requires all blocks co-resident: grid = #SMs, 1 block/SM) ----------------
__device__ __forceinline__ void gsync() {
    __syncthreads();
    if (threadIdx.x == 0) {
        __threadfence();   // membar.gl -> CCTL.IVALL on sm_103a: flushes stores, invalidates L1
        unsigned gen = *((volatile unsigned*)&g_barg);
        unsigned t = atomicAdd(&g_barc, 1u);
        if (t == gridDim.x - 1) {
            g_barc = 0;
            __threadfence();
            atomicAdd(&g_barg, 1u);
        } else {
            while (*((volatile unsigned*)&g_barg) == gen) { __nanosleep(64); }
        }
        __threadfence();
    }
    __syncthreads();
}

// ---------------- shared-memory weight layout (float offsets) ----------------
#define OW1F 0      // [8][16]  W1 rows 0..7  (edge_feat part)
#define OB1  128    // [16]
#define OW1S 144    // [5][16]  W1 rows 8..12 (state part)
#define OW2T 224    // [5][16]  W2 transposed: w2t[c][i] = W2[i][c]
#define OB2  304    // [8]
#define OW3  312    // [5][16]
#define OB3  392    // [16]
#define OW4T 408    // [7][16]  W4 transposed: w4t[c][j] = W4[j][c]
#define OB4  520    // [8]
#define SWSZ 528

extern "C" __global__ void __launch_bounds__(THREADS, 1)
gnn_persistent(const float* __restrict__ edge_feat,
               const int*   __restrict__ edge_src,
               const int*   __restrict__ arc_rows,
               const float* __restrict__ arc_vals,
               const float* __restrict__ state_init,
               const float* __restrict__ old_init,
               const float* __restrict__ W1, const float* __restrict__ b1,
               const float* __restrict__ W2, const float* __restrict__ b2,
               const float* __restrict__ W3, const float* __restrict__ b3,
               const float* __restrict__ W4, const float* __restrict__ b4,
               float* __restrict__ out, int out_size)
{
    __shared__ __align__(16) float sw[SWSZ];
    const int tid  = threadIdx.x;
    const int gtid = blockIdx.x * blockDim.x + tid;
    const int gsz  = gridDim.x * blockDim.x;

    // ---- weights -> smem (zero-pad first) ----
    for (int i = tid; i < SWSZ; i += THREADS) sw[i] = 0.0f;
    __syncthreads();
    for (int i = tid; i < 13 * 15; i += THREADS) {
        int r = i / 15, c = i % 15;
        if (r < 8) sw[OW1F + r * 16 + c] = W1[i];
        else       sw[OW1S + (r - 8) * 16 + c] = W1[i];
    }
    for (int i = tid; i < 15; i += THREADS) sw[OB1 + i] = b1[i];
    for (int i = tid; i < 75; i += THREADS) {           // W2 [15][5] -> w2t[c][i]
        int r = i / 5, c = i % 5;
        sw[OW2T + c * 16 + r] = W2[i];
    }
    for (int i = tid; i < 5;  i += THREADS) sw[OB2 + i] = b2[i];
    for (int i = tid; i < 50; i += THREADS) sw[OW3 + (i / 10) * 16 + (i % 10)] = W3[i];
    for (int i = tid; i < 10; i += THREADS) sw[OB3 + i] = b3[i];
    for (int i = tid; i < 70; i += THREADS) {           // W4 [10][7] -> w4t[c][j]
        int r = i / 7, c = i % 7;
        sw[OW4T + c * 16 + r] = W4[i];
    }
    for (int i = tid; i < 7;  i += THREADS) sw[OB4 + i] = b4[i];
    __syncthreads();

    // ---- pre-phase: flags, state init, per-edge precompute ----
    for (int i = gtid; i < 64; i += gsz) g_flags[i] = 0;

    for (int n = gtid; n < NN; n += gsz) {
        float* p0 = &g_state[0][n * 8];
        float* p1 = &g_state[1][n * 8];
        #pragma unroll
        for (int d = 0; d < 5; ++d) {
            p0[d] = state_init[n * 5 + d];
            p1[d] = old_init[n * 5 + d];
        }
        #pragma unroll
        for (int d = 5; d < 8; ++d) { p0[d] = 0.0f; p1[d] = 0.0f; }
    }

    for (int e = gtid; e < NE; e += gsz) {
        const float4* efp = (const float4*)(edge_feat + (size_t)e * 8);
        float4 f0 = efp[0], f1 = efp[1];
        float ef[8] = {f0.x, f0.y, f0.z, f0.w, f1.x, f1.y, f1.z, f1.w};
        float h[16];
        #pragma unroll
        for (int j = 0; j < 16; ++j) h[j] = sw[OB1 + j];
        #pragma unroll
        for (int f = 0; f < 8; ++f) {
            float s = ef[f];
            const float4* w = (const float4*)&sw[OW1F + f * 16];
            #pragma unroll
            for (int q = 0; q < 4; ++q) {
                float4 wq = w[q];
                h[q * 4 + 0] = fmaf(s, wq.x, h[q * 4 + 0]);
                h[q * 4 + 1] = fmaf(s, wq.y, h[q * 4 + 1]);
                h[q * 4 + 2] = fmaf(s, wq.z, h[q * 4 + 2]);
                h[q * 4 + 3] = fmaf(s, wq.w, h[q * 4 + 3]);
            }
        }
        int src = edge_src[e];
        float4* pp = &g_pre4[(size_t)e * 4];
        pp[0] = make_float4(h[0],  h[1],  h[2],  h[3]);
        pp[1] = make_float4(h[4],  h[5],  h[6],  h[7]);
        pp[2] = make_float4(h[8],  h[9],  h[10], h[11]);
        pp[3] = make_float4(h[12], h[13], h[14], __int_as_float(src));
        g_rv[e] = make_int2(arc_rows[e], __float_as_int(arc_vals[e]));
    }

    gsync();

    // ---- fixed-point iteration loop ----
    int cur = 0;
    int num = 0;
    for (int it = 0; it < MAXIT; ++it) {
        // node phase: dist(state, old), zero old buffer (it becomes the new accumulator)
        const float* sb = g_state[cur];
        float*       ob = g_state[cur ^ 1];
        int flag = 0;
        for (int n = gtid; n < NN; n += gsz) {
            const float4* sp = (const float4*)(sb + n * 8);
            float4*       op = (float4*)(ob + n * 8);
            float4 s0 = sp[0]; float s4 = sb[n * 8 + 4];
            float4 o0 = op[0]; float o4 = ob[n * 8 + 4];
            float d0 = s0.x - o0.x, d1 = s0.y - o0.y, d2 = s0.z - o0.z,
                  d3 = s0.w - o0.w, d4 = s4 - o4;
            float ss = d0*d0 + d1*d1 + d2*d2 + d3*d3 + d4*d4;
            if (sqrtf(ss + 1e-11f) > 0.01f) flag = 1;
            op[0] = make_float4(0.f, 0.f, 0.f, 0.f);
            op[1] = make_float4(0.f, 0.f, 0.f, 0.f);
        }
        int bf = __syncthreads_or(flag);
        if (tid == 0 && bf) atomicOr(&g_flags[it], 1);
        gsync();
        if (g_flags[it] == 0) break;
        num++;

        // edge phase: gather state, MLP, scattered reduction into new buffer
        const float* __restrict__ sbase = g_state[cur];
        float*       __restrict__ dbase = g_state[cur ^ 1];
        for (int e = gtid; e < NE; e += gsz) {
            const float4* pp = &g_pre4[(size_t)e * 4];
            float4 p0 = pp[0], p1 = pp[1], p2 = pp[2], p3 = pp[3];
            int2 rv = g_rv[e];
            int src = __float_as_int(p3.w);
            const float* sp = sbase + src * 8;
            float4 sv = *(const float4*)sp;
            float s4 = sp[4];

            float h[16] = {p0.x, p0.y, p0.z, p0.w,
                           p1.x, p1.y, p1.z, p1.w,
                           p2.x, p2.y, p2.z, p2.w,
                           p3.x, p3.y, p3.z, 0.0f};
            float sd[5] = {sv.x, sv.y, sv.z, sv.w, s4};
            #pragma unroll
            for (int d = 0; d < 5; ++d) {
                float s = sd[d];
                const float4* w = (const float4*)&sw[OW1S + d * 16];
                #pragma unroll
                for (int q = 0; q < 4; ++q) {
                    float4 wq = w[q];
                    h[q * 4 + 0] = fmaf(s, wq.x, h[q * 4 + 0]);
                    h[q * 4 + 1] = fmaf(s, wq.y, h[q * 4 + 1]);
                    h[q * 4 + 2] = fmaf(s, wq.z, h[q * 4 + 2]);
                    h[q * 4 + 3] = fmaf(s, wq.w, h[q * 4 + 3]);
                }
            }
            #pragma unroll
            for (int j = 0; j < 16; ++j) h[j] = fast_tanh(h[j]);

            float val = __int_as_float(rv.y);
            float o[5];
            #pragma unroll
            for (int c = 0; c < 5; ++c) {
                const float4* w = (const float4*)&sw[OW2T + c * 16];
                float acc = sw[OB2 + c];
                #pragma unroll
                for (int q = 0; q < 4; ++q) {
                    float4 wq = w[q];
                    acc = fmaf(h[q * 4 + 0], wq.x, acc);
                    acc = fmaf(h[q * 4 + 1], wq.y, acc);
                    acc = fmaf(h[q * 4 + 2], wq.z, acc);
                    acc = fmaf(h[q * 4 + 3], wq.w, acc);
                }
                o[c] = fast_tanh(acc) * val;
            }
            float* dp = dbase + rv.x * 8;
            asm volatile("red.global.add.v4.f32 [%0], {%1, %2, %3, %4};"
                         :: "l"(dp), "f"(o[0]), "f"(o[1]), "f"(o[2]), "f"(o[3])
                         : "memory");
            atomicAdd(dp + 4, o[4]);
        }
        gsync();
        cur ^= 1;
    }

    // ---- output head: tanh(s@W3+b3) @ W4 + b4 -> softmax ----
    const float* fs = g_state[cur];
    for (int n = gtid; n < NN; n += gsz) {
        const float* sp = fs + n * 8;
        float s0 = sp[0], s1 = sp[1], s2 = sp[2], s3 = sp[3], s4 = sp[4];
        float o1[10];
        #pragma unroll
        for (int j = 0; j < 10; ++j) {
            float a = sw[OB3 + j];
            a = fmaf(s0, sw[OW3 + 0 * 16 + j], a);
            a = fmaf(s1, sw[OW3 + 1 * 16 + j], a);
            a = fmaf(s2, sw[OW3 + 2 * 16 + j], a);
            a = fmaf(s3, sw[OW3 + 3 * 16 + j], a);
            a = fmaf(s4, sw[OW3 + 4 * 16 + j], a);
            o1[j] = fast_tanh(a);
        }
        float lg[7];
        #pragma unroll
        for (int c = 0; c < 7; ++c) {
            float a = sw[OB4 + c];
            #pragma unroll
            for (int j = 0; j < 10; ++j)
                a = fmaf(o1[j], sw[OW4T + c * 16 + j], a);
            lg[c] = a;
        }
        float m = lg[0];
        #pragma unroll
        for (int c = 1; c < 7; ++c) m = fmaxf(m, lg[c]);
        float ex[7], ssum = 0.0f;
        #pragma unroll
        for (int c = 0; c < 7; ++c) { ex[c] = fast_exp(lg[c] - m); ssum += ex[c]; }
        float inv = 1.0f / ssum;
        #pragma unroll
        for (int c = 0; c < 7; ++c) out[(size_t)n * 7 + c] = ex[c] * inv;
    }
    if (gtid == 0 && out_size > NN * 7) out[NN * 7] = (float)num;
}

extern "C" void kernel_launch(void* const* d_in, const int* in_sizes, int n_in,
                              void* d_out, int out_size) {
    (void)in_sizes; (void)n_in;
    int dev = 0, sms = 148;
    if (cudaGetDevice(&dev) == cudaSuccess)
        cudaDeviceGetAttribute(&sms, cudaDevAttrMultiProcessorCount, dev);

    gnn_persistent<<<sms, THREADS>>>(
        (const float*)d_in[0],   // edge_feat
        (const int*)  d_in[1],   // edge_src
        (const int*)  d_in[2],   // arc_rows
        (const float*)d_in[3],   // arc_vals
        (const float*)d_in[4],   // state_init
        (const float*)d_in[5],   // old_state_init
        (const float*)d_in[6],  (const float*)d_in[7],   // W1, b1
        (const float*)d_in[8],  (const float*)d_in[9],   // W2, b2
        (const float*)d_in[10], (const float*)d_in[11],  // W3, b3
        (const float*)d_in[12], (const float*)d_in[13],  // W4, b4
        (float*)d_out, out_size);
}

// round 3
// speedup vs baseline: 1.1319x; 1.1319x over previous
#include <cuda_runtime.h>
#include <math.h>

#define NN 100000
#define NE 1600000
#define NP (NE / 2)
#define MAXIT 50
#define THREADS 384

typedef unsigned long long u64;

// ---------------- device global scratch ----------------
__device__ __align__(16) float     g_state[2][NN * 8];  // padded 8 floats/node (5 used)
__device__ __align__(16) ulonglong2 g_pre[NE * 4];      // 8 f32x2 pairs per edge (15 pre-acts + 0 pad)
__device__ __align__(16) int4      g_rv4[NE];           // {row, val_bits, src, 0}
__device__ unsigned g_barc;
__device__ unsigned g_barg;
__device__ int      g_flags[64];

// ---------------- fast math ----------------
__device__ __forceinline__ float fast_tanh(float x) {
    float t;
    asm("ex2.approx.f32 %0, %1;" : "=f"(t) : "f"(x * 2.885390081777927f)); // exp(2x)
    float r;
    asm("rcp.approx.f32 %0, %1;" : "=f"(r) : "f"(t + 1.0f));
    return fmaf(-2.0f, r, 1.0f);
}
__device__ __forceinline__ float fast_exp(float x) {
    float t;
    asm("ex2.approx.f32 %0, %1;" : "=f"(t) : "f"(x * 1.4426950408889634f));
    return t;
}
__device__ __forceinline__ u64 pack2(float lo, float hi) {
    u64 r;
    asm("mov.b64 %0, {%1, %2};" : "=l"(r) : "f"(lo), "f"(hi));
    return r;
}
__device__ __forceinline__ void unpack2(float& lo, float& hi, u64 v) {
    asm("mov.b64 {%0, %1}, %2;" : "=f"(lo), "=f"(hi) : "l"(v));
}
__device__ __forceinline__ u64 fma2(u64 a, u64 b, u64 c) {
    u64 d;
    asm("fma.rn.f32x2 %0, %1, %2, %3;" : "=l"(d) : "l"(a), "l"(b), "l"(c));
    return d;
}

// ---------------- grid barrier (all blocks co-resident: grid = #SMs, 1 block/SM) ----------------
__device__ __forceinline__ void gsync() {
    __syncthreads();
    if (threadIdx.x == 0) {
        __threadfence();
        unsigned gen = *((volatile unsigned*)&g_barg);
        unsigned t = atomicAdd(&g_barc, 1u);
        if (t == gridDim.x - 1) {
            g_barc = 0;
            __threadfence();
            atomicAdd(&g_barg, 1u);
        } else {
            while (*((volatile unsigned*)&g_barg) == gen) { __nanosleep(32); }
        }
        __threadfence();
    }
    __syncthreads();
}

// ---------------- smem weight layout (float offsets, rows padded to 16) ----------------
#define OW1F 0      // [8][16]  W1 rows 0..7 (edge_feat part)
#define OB1  128    // [16]
#define OW1S 144    // [5][16]  W1 rows 8..12 (state part)
#define OW2T 224    // [5][16]  W2 transposed
#define OB2  304    // [8]
#define OW3  312    // [5][16]
#define OB3  392    // [16]
#define OW4T 408    // [7][16]  W4 transposed
#define OB4  520    // [8]
#define SWSZ 528

// ---------------- edge record ----------------
struct Edge {
    ulonglong2 a0, a1, a2, a3;   // 8 pre-act pairs
    int row, src;
    float val;
    float s0, s1, s2, s3, s4;    // gathered state
};

__device__ __forceinline__ void load_rec(Edge& E, int e) {
    int4 rv = g_rv4[e];
    E.row = rv.x; E.val = __int_as_float(rv.y); E.src = rv.z;
    const ulonglong2* pp = &g_pre[(size_t)e * 4];
    E.a0 = pp[0]; E.a1 = pp[1]; E.a2 = pp[2]; E.a3 = pp[3];
}
__device__ __forceinline__ void load_state(Edge& E, const float* __restrict__ sbase) {
    const float* sp = sbase + E.src * 8;
    float4 sv = *(const float4*)sp;
    E.s0 = sv.x; E.s1 = sv.y; E.s2 = sv.z; E.s3 = sv.w;
    E.s4 = sp[4];
}

__device__ __forceinline__ void compute_scatter_pair(const Edge& A, const Edge& B,
                                                     const float* __restrict__ sw,
                                                     float* __restrict__ dbase) {
    u64 hA[8] = {A.a0.x, A.a0.y, A.a1.x, A.a1.y, A.a2.x, A.a2.y, A.a3.x, A.a3.y};
    u64 hB[8] = {B.a0.x, B.a0.y, B.a1.x, B.a1.y, B.a2.x, B.a2.y, B.a3.x, B.a3.y};
    float sA[5] = {A.s0, A.s1, A.s2, A.s3, A.s4};
    float sB[5] = {B.s0, B.s1, B.s2, B.s3, B.s4};

    // layer 1 (state part): h += s_d * W1S[d][:]
    #pragma unroll
    for (int d = 0; d < 5; ++d) {
        u64 sa = pack2(sA[d], sA[d]);
        u64 sb = pack2(sB[d], sB[d]);
        const ulonglong2* wr = (const ulonglong2*)&sw[OW1S + d * 16];
        #pragma unroll
        for (int q = 0; q < 4; ++q) {
            ulonglong2 w = wr[q];
            hA[2 * q]     = fma2(sa, w.x, hA[2 * q]);
            hA[2 * q + 1] = fma2(sa, w.y, hA[2 * q + 1]);
            hB[2 * q]     = fma2(sb, w.x, hB[2 * q]);
            hB[2 * q + 1] = fma2(sb, w.y, hB[2 * q + 1]);
        }
    }
    // tanh on all 16 lanes (lane 15 is 0 -> stays 0)
    #pragma unroll
    for (int k = 0; k < 8; ++k) {
        float lo, hi;
        unpack2(lo, hi, hA[k]);
        hA[k] = pack2(fast_tanh(lo), fast_tanh(hi));
        unpack2(lo, hi, hB[k]);
        hB[k] = pack2(fast_tanh(lo), fast_tanh(hi));
    }
    // layer 2: o[c] = tanh(b2[c] + h . W2T[c][:]) * val
    float oA[5], oB[5];
    #pragma unroll
    for (int c = 0; c < 5; ++c) {
        const ulonglong2* wr = (const ulonglong2*)&sw[OW2T + c * 16];
        u64 aA0 = 0ull, aA1 = 0ull, aB0 = 0ull, aB1 = 0ull;
        #pragma unroll
        for (int q = 0; q < 4; ++q) {
            ulonglong2 w = wr[q];
            aA0 = fma2(hA[2 * q],     w.x, aA0);
            aA1 = fma2(hA[2 * q + 1], w.y, aA1);
            aB0 = fma2(hB[2 * q],     w.x, aB0);
            aB1 = fma2(hB[2 * q + 1], w.y, aB1);
        }
        float b2c = sw[OB2 + c];
        float x0, x1, y0, y1;
        unpack2(x0, x1, aA0); unpack2(y0, y1, aA1);
        float accA = b2c + ((x0 + x1) + (y0 + y1));
        unpack2(x0, x1, aB0); unpack2(y0, y1, aB1);
        float accB = b2c + ((x0 + x1) + (y0 + y1));
        oA[c] = fast_tanh(accA) * A.val;
        oB[c] = fast_tanh(accB) * B.val;
    }
    float* dpA = dbase + (size_t)A.row * 8;
    asm volatile("red.global.add.v4.f32 [%0], {%1, %2, %3, %4};"
                 :: "l"(dpA), "f"(oA[0]), "f"(oA[1]), "f"(oA[2]), "f"(oA[3]) : "memory");
    atomicAdd(dpA + 4, oA[4]);
    float* dpB = dbase + (size_t)B.row * 8;
    asm volatile("red.global.add.v4.f32 [%0], {%1, %2, %3, %4};"
                 :: "l"(dpB), "f"(oB[0]), "f"(oB[1]), "f"(oB[2]), "f"(oB[3]) : "memory");
    atomicAdd(dpB + 4, oB[4]);
}

extern "C" __global__ void __launch_bounds__(THREADS, 1)
gnn_persistent(const float* __restrict__ edge_feat,
               const int*   __restrict__ edge_src,
               const int*   __restrict__ arc_rows,
               const float* __restrict__ arc_vals,
               const float* __restrict__ state_init,
               const float* __restrict__ old_init,
               const float* __restrict__ W1, const float* __restrict__ b1,
               const float* __restrict__ W2, const float* __restrict__ b2,
               const float* __restrict__ W3, const float* __restrict__ b3,
               const float* __restrict__ W4, const float* __restrict__ b4,
               float* __restrict__ out, int out_size)
{
    __shared__ __align__(16) float sw[SWSZ];
    const int tid  = threadIdx.x;
    const int gtid = blockIdx.x * blockDim.x + tid;
    const int gsz  = gridDim.x * blockDim.x;

    // ---- weights -> smem ----
    for (int i = tid; i < SWSZ; i += THREADS) sw[i] = 0.0f;
    __syncthreads();
    for (int i = tid; i < 13 * 15; i += THREADS) {
        int r = i / 15, c = i % 15;
        if (r < 8) sw[OW1F + r * 16 + c] = W1[i];
        else       sw[OW1S + (r - 8) * 16 + c] = W1[i];
    }
    for (int i = tid; i < 15; i += THREADS) sw[OB1 + i] = b1[i];
    for (int i = tid; i < 75; i += THREADS) sw[OW2T + (i % 5) * 16 + (i / 5)] = W2[i];
    for (int i = tid; i < 5;  i += THREADS) sw[OB2 + i] = b2[i];
    for (int i = tid; i < 50; i += THREADS) sw[OW3 + (i / 10) * 16 + (i % 10)] = W3[i];
    for (int i = tid; i < 10; i += THREADS) sw[OB3 + i] = b3[i];
    for (int i = tid; i < 70; i += THREADS) sw[OW4T + (i % 7) * 16 + (i / 7)] = W4[i];
    for (int i = tid; i < 7;  i += THREADS) sw[OB4 + i] = b4[i];
    __syncthreads();

    // ---- pre-phase ----
    for (int i = gtid; i < 64; i += gsz) g_flags[i] = 0;

    for (int n = gtid; n < NN; n += gsz) {
        float* p0 = &g_state[0][n * 8];
        float* p1 = &g_state[1][n * 8];
        #pragma unroll
        for (int d = 0; d < 5; ++d) {
            p0[d] = state_init[n * 5 + d];
            p1[d] = old_init[n * 5 + d];
        }
        #pragma unroll
        for (int d = 5; d < 8; ++d) { p0[d] = 0.0f; p1[d] = 0.0f; }
    }

    for (int e = gtid; e < NE; e += gsz) {
        const float4* efp = (const float4*)(edge_feat + (size_t)e * 8);
        float4 f0 = efp[0], f1 = efp[1];
        float ef[8] = {f0.x, f0.y, f0.z, f0.w, f1.x, f1.y, f1.z, f1.w};
        float h[16];
        #pragma unroll
        for (int j = 0; j < 16; ++j) h[j] = sw[OB1 + j];
        #pragma unroll
        for (int f = 0; f < 8; ++f) {
            float s = ef[f];
            const float4* w = (const float4*)&sw[OW1F + f * 16];
            #pragma unroll
            for (int q = 0; q < 4; ++q) {
                float4 wq = w[q];
                h[q * 4 + 0] = fmaf(s, wq.x, h[q * 4 + 0]);
                h[q * 4 + 1] = fmaf(s, wq.y, h[q * 4 + 1]);
                h[q * 4 + 2] = fmaf(s, wq.z, h[q * 4 + 2]);
                h[q * 4 + 3] = fmaf(s, wq.w, h[q * 4 + 3]);
            }
        }
        h[15] = 0.0f;  // pad lane must be exactly 0
        ulonglong2* pp = &g_pre[(size_t)e * 4];
        ulonglong2 t;
        t.x = pack2(h[0],  h[1]);  t.y = pack2(h[2],  h[3]);  pp[0] = t;
        t.x = pack2(h[4],  h[5]);  t.y = pack2(h[6],  h[7]);  pp[1] = t;
        t.x = pack2(h[8],  h[9]);  t.y = pack2(h[10], h[11]); pp[2] = t;
        t.x = pack2(h[12], h[13]); t.y = pack2(h[14], h[15]); pp[3] = t;
        g_rv4[e] = make_int4(arc_rows[e], __float_as_int(arc_vals[e]), edge_src[e], 0);
    }

    gsync();

    // ---- fixed-point loop ----
    int cur = 0;
    int num = 0;
    for (int it = 0; it < MAXIT; ++it) {
        // node phase: dist + zero old buffer (becomes new accumulator)
        const float* sb = g_state[cur];
        float*       ob = g_state[cur ^ 1];
        int flag = 0;
        for (int n = gtid; n < NN; n += gsz) {
            const float4* sp = (const float4*)(sb + n * 8);
            float4*       op = (float4*)(ob + n * 8);
            float4 s0 = sp[0]; float s4 = sb[n * 8 + 4];
            float4 o0 = op[0]; float o4 = ob[n * 8 + 4];
            float d0 = s0.x - o0.x, d1 = s0.y - o0.y, d2 = s0.z - o0.z,
                  d3 = s0.w - o0.w, d4 = s4 - o4;
            float ss = d0*d0 + d1*d1 + d2*d2 + d3*d3 + d4*d4;
            if (sqrtf(ss + 1e-11f) > 0.01f) flag = 1;
            op[0] = make_float4(0.f, 0.f, 0.f, 0.f);
            op[1] = make_float4(0.f, 0.f, 0.f, 0.f);
        }
        int bf = __syncthreads_or(flag);
        if (tid == 0 && bf) atomicOr(&g_flags[it], 1);
        gsync();
        if (*((volatile int*)&g_flags[it]) == 0) break;
        num++;

        // edge phase: prefetched, 2 edges/thread, f32x2 MLP, scattered reduction
        const float* __restrict__ sbase = g_state[cur];
        float*       __restrict__ dbase = g_state[cur ^ 1];

        int i = gtid;
        Edge cA, cB;
        if (i < NP) {
            load_rec(cA, i); load_rec(cB, i + NP);
            load_state(cA, sbase); load_state(cB, sbase);
        }
        for (; i < NP; i += gsz) {
            int j = i + gsz;
            int jj = (j < NP) ? j : i;
            Edge nA, nB;
            load_rec(nA, jj); load_rec(nB, jj + NP);
            load_state(nA, sbase); load_state(nB, sbase);
            compute_scatter_pair(cA, cB, sw, dbase);
            cA = nA; cB = nB;
        }
        gsync();
        cur ^= 1;
    }

    // ---- output head ----
    const float* fs = g_state[cur];
    for (int n = gtid; n < NN; n += gsz) {
        const float* sp = fs + n * 8;
        float s0 = sp[0], s1 = sp[1], s2 = sp[2], s3 = sp[3], s4 = sp[4];
        float o1[10];
        #pragma unroll
        for (int j = 0; j < 10; ++j) {
            float a = sw[OB3 + j];
            a = fmaf(s0, sw[OW3 + 0 * 16 + j], a);
            a = fmaf(s1, sw[OW3 + 1 * 16 + j], a);
            a = fmaf(s2, sw[OW3 + 2 * 16 + j], a);
            a = fmaf(s3, sw[OW3 + 3 * 16 + j], a);
            a = fmaf(s4, sw[OW3 + 4 * 16 + j], a);
            o1[j] = fast_tanh(a);
        }
        float lg[7];
        #pragma unroll
        for (int c = 0; c < 7; ++c) {
            float a = sw[OB4 + c];
            #pragma unroll
            for (int j = 0; j < 10; ++j)
                a = fmaf(o1[j], sw[OW4T + c * 16 + j], a);
            lg[c] = a;
        }
        float m = lg[0];
        #pragma unroll
        for (int c = 1; c < 7; ++c) m = fmaxf(m, lg[c]);
        float ex[7], ssum = 0.0f;
        #pragma unroll
        for (int c = 0; c < 7; ++c) { ex[c] = fast_exp(lg[c] - m); ssum += ex[c]; }
        float inv = 1.0f / ssum;
        #pragma unroll
        for (int c = 0; c < 7; ++c) out[(size_t)n * 7 + c] = ex[c] * inv;
    }
    if (gtid == 0 && out_size > NN * 7) out[NN * 7] = (float)num;
}

extern "C" void kernel_launch(void* const* d_in, const int* in_sizes, int n_in,
                              void* d_out, int out_size) {
    (void)in_sizes; (void)n_in;
    int dev = 0, sms = 148;
    if (cudaGetDevice(&dev) == cudaSuccess)
        cudaDeviceGetAttribute(&sms, cudaDevAttrMultiProcessorCount, dev);

    gnn_persistent<<<sms, THREADS>>>(
        (const float*)d_in[0],
        (const int*)  d_in[1],
        (const int*)  d_in[2],
        (const float*)d_in[3],
        (const float*)d_in[4],
        (const float*)d_in[5],
        (const float*)d_in[6],  (const float*)d_in[7],
        (const float*)d_in[8],  (const float*)d_in[9],
        (const float*)d_in[10], (const float*)d_in[11],
        (const float*)d_in[12], (const float*)d_in[13],
        (float*)d_out, out_size);
}